// round 2
// baseline (speedup 1.0000x reference)
#include <cuda_runtime.h>
#include <cstddef>

#define HDIM 64
#define NMAX 100352

// ---------------- scratch (static device globals; no allocation allowed) ----
__device__ float g_aggu[(size_t)NMAX * HDIM];
__device__ float g_aggb[(size_t)NMAX * HDIM];
__device__ float g_y1u[(size_t)NMAX * HDIM];
__device__ float g_y1b[(size_t)NMAX * HDIM];
__device__ float g_y2[(size_t)NMAX * 2 * HDIM];
__device__ float g_stats[5 * 128];     // per BN: [0..63]=sum, [64..127]=sumsq
__device__ float g_sc1u[64], g_sh1u[64];
__device__ float g_sc1b[64], g_sh1b[64];
__device__ float g_sc2[128], g_sh2[128];
__device__ float g_sc3[64],  g_sh3[64];

// ---------------- init: agg = (1+eps)*x, zero stats ------------------------
__global__ void init_kernel(const float* __restrict__ x,
                            const float* __restrict__ eps1,
                            const float* __restrict__ eps2,
                            float* __restrict__ aggu,
                            float* __restrict__ aggb,
                            float* __restrict__ stats,
                            int total4)
{
    int i = blockIdx.x * blockDim.x + threadIdx.x;
    if (i < 5 * 128) stats[i] = 0.0f;
    float a = 1.0f + __ldg(eps1);
    float b = 1.0f + __ldg(eps2);
    const float4* x4 = (const float4*)x;
    float4* u4 = (float4*)aggu;
    float4* b4 = (float4*)aggb;
    int stride = gridDim.x * blockDim.x;
    for (int t = i; t < total4; t += stride) {
        float4 v = x4[t];
        float4 r;
        r.x = a * v.x; r.y = a * v.y; r.z = a * v.z; r.w = a * v.w;
        u4[t] = r;
        float4 s;
        s.x = b * v.x; s.y = b * v.y; s.z = b * v.z; s.w = b * v.w;
        b4[t] = s;
    }
}

// ---------------- scatter-add: agg[dst[e]] += feat[src[e]] ------------------
__global__ void scatter_kernel(const float* __restrict__ feat,
                               const int* __restrict__ dst_idx,
                               const int* __restrict__ src_idx,
                               int E,
                               float* __restrict__ agg)
{
    int gw   = (blockIdx.x * blockDim.x + threadIdx.x) >> 5;
    int lane = threadIdx.x & 31;
    int nw   = (gridDim.x * blockDim.x) >> 5;
    for (int e = gw; e < E; e += nw) {
        int dst = __ldg(&dst_idx[e]);
        int src = __ldg(&src_idx[e]);
        const float* s = feat + (size_t)src * HDIM;
        float* d = agg + (size_t)dst * HDIM;
        float v0 = __ldg(&s[lane]);
        float v1 = __ldg(&s[lane + 32]);
        atomicAdd(&d[lane], v0);
        atomicAdd(&d[lane + 32], v1);
    }
}

// ---------------- GEMM + bias + (fused input BN-affine+ReLU) + BN stats -----
// Y[i][j] = sum_k act(A[i][k]) * W[k][j] + bias[j]
// act(v)   = inScale ? relu(v*inScale[k] + inShift[k]) : v
// stats[j] += sum_i Y[i][j];  stats[64+j] += sum_i Y[i][j]^2
// Block tile: 128 rows x 64 cols, 128 threads, 8x8 per thread.
template <int K>
__global__ void gemm_bn(const float* __restrict__ A,
                        const float* __restrict__ W,
                        const float* __restrict__ bias,
                        const float* __restrict__ inScale,
                        const float* __restrict__ inShift,
                        float* __restrict__ Y, int ldY,
                        float* __restrict__ stats,
                        int N)
{
    __shared__ float As[32][132];   // transposed A chunk
    __shared__ float Ws[32][68];    // W chunk
    __shared__ float sstat[128];

    const int tid = threadIdx.x;          // 0..127
    const int tx  = tid & 15;             // row group (8 rows each)
    const int ty  = tid >> 4;             // col group (8 cols each), 0..7
    const int rbase = blockIdx.x * 128;
    const bool aff = (inScale != nullptr);

    sstat[tid] = 0.0f;

    float acc[8][8];
#pragma unroll
    for (int i = 0; i < 8; i++)
#pragma unroll
        for (int j = 0; j < 8; j++) acc[i][j] = 0.0f;

    for (int kc = 0; kc < K; kc += 32) {
        // --- load A chunk (128 rows x 32 cols), transpose, fused affine+relu
#pragma unroll
        for (int it = 0; it < 8; it++) {
            int lin = it * 128 + tid;     // 1024 float4 slots -> 4096 floats
            int r   = lin >> 3;           // 8 float4 per row
            int c4  = lin & 7;
            int gr  = rbase + r;
            float4 v = make_float4(0.f, 0.f, 0.f, 0.f);
            if (gr < N)
                v = *(const float4*)&A[(size_t)gr * K + kc + c4 * 4];
            if (aff) {
                int c = kc + c4 * 4;
                v.x = fmaxf(v.x * inScale[c + 0] + inShift[c + 0], 0.f);
                v.y = fmaxf(v.y * inScale[c + 1] + inShift[c + 1], 0.f);
                v.z = fmaxf(v.z * inScale[c + 2] + inShift[c + 2], 0.f);
                v.w = fmaxf(v.w * inScale[c + 3] + inShift[c + 3], 0.f);
            }
            As[c4 * 4 + 0][r] = v.x;
            As[c4 * 4 + 1][r] = v.y;
            As[c4 * 4 + 2][r] = v.z;
            As[c4 * 4 + 3][r] = v.w;
        }
        // --- load W chunk (32 rows x 64 cols)
#pragma unroll
        for (int it = 0; it < 4; it++) {
            int lin = it * 128 + tid;     // 512 float4 -> 2048 floats
            int r   = lin >> 4;           // 16 float4 per row
            int c4  = lin & 15;
            float4 w = *(const float4*)&W[(size_t)(kc + r) * 64 + c4 * 4];
            *(float4*)&Ws[r][c4 * 4] = w;
        }
        __syncthreads();

        // --- compute
#pragma unroll
        for (int k = 0; k < 32; k++) {
            float a[8], w[8];
            *(float4*)&a[0] = *(const float4*)&As[k][tx * 8];
            *(float4*)&a[4] = *(const float4*)&As[k][tx * 8 + 4];
            *(float4*)&w[0] = *(const float4*)&Ws[k][ty * 8];
            *(float4*)&w[4] = *(const float4*)&Ws[k][ty * 8 + 4];
#pragma unroll
            for (int i = 0; i < 8; i++)
#pragma unroll
                for (int j = 0; j < 8; j++)
                    acc[i][j] += a[i] * w[j];
        }
        __syncthreads();
    }

    // --- epilogue: bias, store, stats
    float b[8];
    *(float4*)&b[0] = *(const float4*)&bias[ty * 8];
    *(float4*)&b[4] = *(const float4*)&bias[ty * 8 + 4];

    float psum[8], psq[8];
#pragma unroll
    for (int j = 0; j < 8; j++) { psum[j] = 0.f; psq[j] = 0.f; }

#pragma unroll
    for (int i = 0; i < 8; i++) {
        int gr = rbase + tx * 8 + i;
        if (gr < N) {
            float v[8];
#pragma unroll
            for (int j = 0; j < 8; j++) {
                v[j] = acc[i][j] + b[j];
                psum[j] += v[j];
                psq[j]  += v[j] * v[j];
            }
            float* yp = &Y[(size_t)gr * ldY + ty * 8];
            *(float4*)&yp[0] = *(float4*)&v[0];
            *(float4*)&yp[4] = *(float4*)&v[4];
        }
    }
#pragma unroll
    for (int j = 0; j < 8; j++) {
        atomicAdd(&sstat[ty * 8 + j], psum[j]);
        atomicAdd(&sstat[64 + ty * 8 + j], psq[j]);
    }
    __syncthreads();
    atomicAdd(&stats[tid], sstat[tid]);
}

// ---------------- BN coefficients: scale = g*rstd, shift = be - mean*scale --
__global__ void coeffs_kernel(const float* __restrict__ stats,
                              const float* __restrict__ g,
                              const float* __restrict__ be,
                              float* __restrict__ scale,
                              float* __restrict__ shift,
                              float invN)
{
    int j = threadIdx.x;
    if (j < 64) {
        float mean = stats[j] * invN;
        float var  = stats[64 + j] * invN - mean * mean;
        float rstd = rsqrtf(var + 1e-5f);
        float s = g[j] * rstd;
        scale[j] = s;
        shift[j] = be[j] - mean * s;
    }
}

// ---------------- final in-place BN + ReLU ---------------------------------
__global__ void bnrelu_kernel(float* __restrict__ Y,
                              const float* __restrict__ scale,
                              const float* __restrict__ shift,
                              int total4)
{
    int i = blockIdx.x * blockDim.x + threadIdx.x;
    int stride = gridDim.x * blockDim.x;
    float4* y4 = (float4*)Y;
    for (int t = i; t < total4; t += stride) {
        int c = (t * 4) & 63;
        float4 v = y4[t];
        float4 s = *(const float4*)&scale[c];
        float4 h = *(const float4*)&shift[c];
        v.x = fmaxf(v.x * s.x + h.x, 0.f);
        v.y = fmaxf(v.y * s.y + h.y, 0.f);
        v.z = fmaxf(v.z * s.z + h.z, 0.f);
        v.w = fmaxf(v.w * s.w + h.w, 0.f);
        y4[t] = v;
    }
}

// ---------------- launch ----------------------------------------------------
extern "C" void kernel_launch(void* const* d_in, const int* in_sizes, int n_in,
                              void* d_out, int out_size)
{
    const float* x     = (const float*)d_in[0];
    const float* battr = (const float*)d_in[1];
    const int*   upidx = (const int*)d_in[2];
    const int*   bidx  = (const int*)d_in[3];
    const float* eps1  = (const float*)d_in[4];
    const float* eps2  = (const float*)d_in[5];
    const float* uw1 = (const float*)d_in[6];
    const float* ub1 = (const float*)d_in[7];
    const float* ug1 = (const float*)d_in[8];
    const float* ube1= (const float*)d_in[9];
    const float* uw2 = (const float*)d_in[10];
    const float* ub2 = (const float*)d_in[11];
    const float* ug2 = (const float*)d_in[12];
    const float* ube2= (const float*)d_in[13];
    const float* bw1 = (const float*)d_in[14];
    const float* bb1 = (const float*)d_in[15];
    const float* bg1 = (const float*)d_in[16];
    const float* bbe1= (const float*)d_in[17];
    const float* bw2 = (const float*)d_in[18];
    const float* bb2 = (const float*)d_in[19];
    const float* bg2 = (const float*)d_in[20];
    const float* bbe2= (const float*)d_in[21];
    const float* cw  = (const float*)d_in[22];
    const float* cb  = (const float*)d_in[23];
    const float* cg  = (const float*)d_in[24];
    const float* cbe = (const float*)d_in[25];
    float* out = (float*)d_out;

    int N  = in_sizes[0] / HDIM;
    int EU = in_sizes[2] / 2;
    int EB = in_sizes[3] / 2;

    float *aggu, *aggb, *y1u, *y1b, *y2, *stats;
    float *sc1u, *sh1u, *sc1b, *sh1b, *sc2, *sh2, *sc3, *sh3;
    cudaGetSymbolAddress((void**)&aggu,  g_aggu);
    cudaGetSymbolAddress((void**)&aggb,  g_aggb);
    cudaGetSymbolAddress((void**)&y1u,   g_y1u);
    cudaGetSymbolAddress((void**)&y1b,   g_y1b);
    cudaGetSymbolAddress((void**)&y2,    g_y2);
    cudaGetSymbolAddress((void**)&stats, g_stats);
    cudaGetSymbolAddress((void**)&sc1u,  g_sc1u);
    cudaGetSymbolAddress((void**)&sh1u,  g_sh1u);
    cudaGetSymbolAddress((void**)&sc1b,  g_sc1b);
    cudaGetSymbolAddress((void**)&sh1b,  g_sh1b);
    cudaGetSymbolAddress((void**)&sc2,   g_sc2);
    cudaGetSymbolAddress((void**)&sh2,   g_sh2);
    cudaGetSymbolAddress((void**)&sc3,   g_sc3);
    cudaGetSymbolAddress((void**)&sh3,   g_sh3);

    float invN = 1.0f / (float)N;
    int total4 = (N * HDIM) / 4;
    int gb = (N + 127) / 128;

    // Phase 0: init aggregates + zero stats
    init_kernel<<<592, 256>>>(x, eps1, eps2, aggu, aggb, stats, total4);

    // Phase 1: scatter-adds
    // up:       agg_up[up_index[0][e]]       += x[up_index[1][e]]
    // boundary: agg_b [boundary_index[1][e]] += battr[boundary_index[0][e]]
    scatter_kernel<<<4736, 256>>>(x,     upidx,     upidx + EU, EU, aggu);
    scatter_kernel<<<1184, 256>>>(battr, bidx + EB, bidx,       EB, aggb);

    // Phase 2: layer-1 GEMMs (+ BN stats)
    gemm_bn<64><<<gb, 128>>>(aggu, uw1, ub1, nullptr, nullptr, y1u, 64, stats + 0,   N);
    gemm_bn<64><<<gb, 128>>>(aggb, bw1, bb1, nullptr, nullptr, y1b, 64, stats + 128, N);
    coeffs_kernel<<<1, 64>>>(stats + 0,   ug1, ube1, sc1u, sh1u, invN);
    coeffs_kernel<<<1, 64>>>(stats + 128, bg1, bbe1, sc1b, sh1b, invN);

    // Phase 3: layer-2 GEMMs with fused BN+ReLU on input; outputs interleave
    // into y2[N][128] (u -> cols 0..63, b -> cols 64..127)
    gemm_bn<64><<<gb, 128>>>(y1u, uw2, ub2, sc1u, sh1u, y2,      128, stats + 256, N);
    gemm_bn<64><<<gb, 128>>>(y1b, bw2, bb2, sc1b, sh1b, y2 + 64, 128, stats + 384, N);
    coeffs_kernel<<<1, 64>>>(stats + 256, ug2, ube2, sc2,      sh2,      invN);
    coeffs_kernel<<<1, 64>>>(stats + 384, bg2, bbe2, sc2 + 64, sh2 + 64, invN);

    // Phase 4: combine GEMM (K=128) with fused BN+ReLU on input, write to out
    gemm_bn<128><<<gb, 128>>>(y2, cw, cb, sc2, sh2, out, 64, stats + 512, N);
    coeffs_kernel<<<1, 64>>>(stats + 512, cg, cbe, sc3, sh3, invN);

    // Phase 5: final BN+ReLU in place on out
    bnrelu_kernel<<<592, 256>>>(out, sc3, sh3, total4);
}

// round 3
// speedup vs baseline: 1.1500x; 1.1500x over previous
#include <cuda_runtime.h>
#include <cstddef>

#define HDIM 64
#define NMAX 100352

// ---------------- scratch (static device globals; no allocation allowed) ----
__device__ float g_aggu[(size_t)NMAX * HDIM];
__device__ float g_aggb[(size_t)NMAX * HDIM];
__device__ float g_y1u[(size_t)NMAX * HDIM];
__device__ float g_y1b[(size_t)NMAX * HDIM];
__device__ float g_y2[(size_t)NMAX * 2 * HDIM];
__device__ float g_stats[5 * 128];     // per BN: [0..63]=sum, [64..127]=sumsq
__device__ float g_sc1u[64], g_sh1u[64];
__device__ float g_sc1b[64], g_sh1b[64];
__device__ float g_sc2[128], g_sh2[128];
__device__ float g_sc3[64],  g_sh3[64];

// ---------------- init: agg = (1+eps)*x, zero stats ------------------------
__global__ void init_kernel(const float* __restrict__ x,
                            const float* __restrict__ eps1,
                            const float* __restrict__ eps2,
                            float* __restrict__ aggu,
                            float* __restrict__ aggb,
                            float* __restrict__ stats,
                            int total4)
{
    int i = blockIdx.x * blockDim.x + threadIdx.x;
    if (i < 5 * 128) stats[i] = 0.0f;
    float a = 1.0f + __ldg(eps1);
    float b = 1.0f + __ldg(eps2);
    const float4* x4 = (const float4*)x;
    float4* u4 = (float4*)aggu;
    float4* b4 = (float4*)aggb;
    int stride = gridDim.x * blockDim.x;
    for (int t = i; t < total4; t += stride) {
        float4 v = x4[t];
        float4 r;
        r.x = a * v.x; r.y = a * v.y; r.z = a * v.z; r.w = a * v.w;
        u4[t] = r;
        float4 s;
        s.x = b * v.x; s.y = b * v.y; s.z = b * v.z; s.w = b * v.w;
        b4[t] = s;
    }
}

// ---------------- scatter-add: agg[dst[e]] += feat[src[e]] ------------------
// Work item = one 16-byte chunk of one edge. 16 chunks per edge (H=64).
// Vectorized reduction: 1 LDG.128 + 1 RED.ADD.v4 per chunk.
__global__ void scatter_kernel(const float* __restrict__ feat,
                               const int* __restrict__ dst_idx,
                               const int* __restrict__ src_idx,
                               int E,
                               float* __restrict__ agg)
{
    long t = blockIdx.x * (long)blockDim.x + threadIdx.x;
    long stride = gridDim.x * (long)blockDim.x;
    long total = (long)E * 16;
    for (long i = t; i < total; i += stride) {
        int e = (int)(i >> 4);
        int c = (int)(i & 15);
        int dst = __ldg(&dst_idx[e]);
        int src = __ldg(&src_idx[e]);
        float4 v = *(const float4*)(feat + ((size_t)src << 6) + c * 4);
        float* p = agg + ((size_t)dst << 6) + c * 4;
        asm volatile("red.global.add.v4.f32 [%0], {%1,%2,%3,%4};"
                     :: "l"(p), "f"(v.x), "f"(v.y), "f"(v.z), "f"(v.w)
                     : "memory");
    }
}

// ---------------- GEMM + bias + (fused input BN-affine+ReLU) + BN stats -----
// Y[i][j] = sum_k act(A[i][k]) * W[k][j] + bias[j]
// act(v)   = AFF ? relu(v*inScale[k] + inShift[k]) : v
// stats[j] += sum_i Y[i][j];  stats[64+j] += sum_i Y[i][j]^2
// Tile: 128 rows x 64 cols, 256 threads, 4x8 per thread, K-chunks of 32.
template <int K, bool AFF>
__global__ __launch_bounds__(256, 4)
void gemm_bn(const float* __restrict__ A,
             const float* __restrict__ W,
             const float* __restrict__ bias,
             const float* __restrict__ inScale,
             const float* __restrict__ inShift,
             float* __restrict__ Y, int ldY,
             float* __restrict__ stats,
             int N)
{
    __shared__ float As[32][132];   // transposed A chunk: As[k][row]
    __shared__ float Ws[32][64];    // W chunk: Ws[k][col]

    const int tid = threadIdx.x;          // 0..255
    const int tx  = tid & 31;             // row group (4 rows each), 0..31
    const int ty  = tid >> 5;             // col group (8 cols each), 0..7
    const int rbase = blockIdx.x * 128;

    float acc[4][8];
#pragma unroll
    for (int i = 0; i < 4; i++)
#pragma unroll
        for (int j = 0; j < 8; j++) acc[i][j] = 0.0f;

#pragma unroll
    for (int kc = 0; kc < K; kc += 32) {
        // --- load A chunk (128 rows x 32 cols), transform, transpose-store
#pragma unroll
        for (int it = 0; it < 4; it++) {
            int lin = it * 256 + tid;     // 1024 float4 slots
            int r   = lin >> 3;           // 8 float4 per row
            int c4  = lin & 7;
            int gr  = rbase + r;
            float4 v = make_float4(0.f, 0.f, 0.f, 0.f);
            if (gr < N)
                v = *(const float4*)&A[(size_t)gr * K + kc + c4 * 4];
            if (AFF) {
                int c = kc + c4 * 4;
                v.x = fmaxf(v.x * __ldg(&inScale[c + 0]) + __ldg(&inShift[c + 0]), 0.f);
                v.y = fmaxf(v.y * __ldg(&inScale[c + 1]) + __ldg(&inShift[c + 1]), 0.f);
                v.z = fmaxf(v.z * __ldg(&inScale[c + 2]) + __ldg(&inShift[c + 2]), 0.f);
                v.w = fmaxf(v.w * __ldg(&inScale[c + 3]) + __ldg(&inShift[c + 3]), 0.f);
            }
            As[c4 * 4 + 0][r] = v.x;
            As[c4 * 4 + 1][r] = v.y;
            As[c4 * 4 + 2][r] = v.z;
            As[c4 * 4 + 3][r] = v.w;
        }
        // --- load W chunk (32 rows x 64 cols)
#pragma unroll
        for (int it = 0; it < 2; it++) {
            int lin = it * 256 + tid;     // 512 float4
            int r   = lin >> 4;           // 16 float4 per row
            int c4  = lin & 15;
            *(float4*)&Ws[r][c4 * 4] = *(const float4*)&W[(size_t)(kc + r) * 64 + c4 * 4];
        }
        __syncthreads();

        // --- compute
#pragma unroll
        for (int k = 0; k < 32; k++) {
            float a[4], w[8];
            *(float4*)&a[0] = *(const float4*)&As[k][tx * 4];
            *(float4*)&w[0] = *(const float4*)&Ws[k][ty * 8];
            *(float4*)&w[4] = *(const float4*)&Ws[k][ty * 8 + 4];
#pragma unroll
            for (int i = 0; i < 4; i++)
#pragma unroll
                for (int j = 0; j < 8; j++)
                    acc[i][j] += a[i] * w[j];
        }
        if (kc + 32 < K) __syncthreads();
    }

    // --- epilogue: bias, store, per-warp stats reduction
    float b[8];
    *(float4*)&b[0] = *(const float4*)&bias[ty * 8];
    *(float4*)&b[4] = *(const float4*)&bias[ty * 8 + 4];

    float psum[8], psq[8];
#pragma unroll
    for (int j = 0; j < 8; j++) { psum[j] = 0.f; psq[j] = 0.f; }

#pragma unroll
    for (int i = 0; i < 4; i++) {
        int gr = rbase + tx * 4 + i;
        if (gr < N) {
            float v[8];
#pragma unroll
            for (int j = 0; j < 8; j++) {
                v[j] = acc[i][j] + b[j];
                psum[j] += v[j];
                psq[j]  += v[j] * v[j];
            }
            float* yp = &Y[(size_t)gr * ldY + ty * 8];
            *(float4*)&yp[0] = *(float4*)&v[0];
            *(float4*)&yp[4] = *(float4*)&v[4];
        }
    }
    // warp-wide reduce (all lanes participate; OOB rows contributed 0)
#pragma unroll
    for (int j = 0; j < 8; j++) {
#pragma unroll
        for (int o = 16; o > 0; o >>= 1) {
            psum[j] += __shfl_xor_sync(0xFFFFFFFFu, psum[j], o);
            psq[j]  += __shfl_xor_sync(0xFFFFFFFFu, psq[j],  o);
        }
    }
    if (tx == 0) {
#pragma unroll
        for (int j = 0; j < 8; j++) {
            atomicAdd(&stats[ty * 8 + j], psum[j]);
            atomicAdd(&stats[64 + ty * 8 + j], psq[j]);
        }
    }
}

// ---------------- BN coefficients: scale = g*rstd, shift = be - mean*scale --
__global__ void coeffs_kernel(const float* __restrict__ stats,
                              const float* __restrict__ g,
                              const float* __restrict__ be,
                              float* __restrict__ scale,
                              float* __restrict__ shift,
                              float invN)
{
    int j = threadIdx.x;
    if (j < 64) {
        float mean = stats[j] * invN;
        float var  = stats[64 + j] * invN - mean * mean;
        float rstd = rsqrtf(var + 1e-5f);
        float s = g[j] * rstd;
        scale[j] = s;
        shift[j] = be[j] - mean * s;
    }
}

// ---------------- final in-place BN + ReLU ---------------------------------
__global__ void bnrelu_kernel(float* __restrict__ Y,
                              const float* __restrict__ scale,
                              const float* __restrict__ shift,
                              int total4)
{
    int i = blockIdx.x * blockDim.x + threadIdx.x;
    int stride = gridDim.x * blockDim.x;
    float4* y4 = (float4*)Y;
    for (int t = i; t < total4; t += stride) {
        int c = (t * 4) & 63;
        float4 v = y4[t];
        float4 s = *(const float4*)&scale[c];
        float4 h = *(const float4*)&shift[c];
        v.x = fmaxf(v.x * s.x + h.x, 0.f);
        v.y = fmaxf(v.y * s.y + h.y, 0.f);
        v.z = fmaxf(v.z * s.z + h.z, 0.f);
        v.w = fmaxf(v.w * s.w + h.w, 0.f);
        y4[t] = v;
    }
}

// ---------------- launch ----------------------------------------------------
extern "C" void kernel_launch(void* const* d_in, const int* in_sizes, int n_in,
                              void* d_out, int out_size)
{
    const float* x     = (const float*)d_in[0];
    const float* battr = (const float*)d_in[1];
    const int*   upidx = (const int*)d_in[2];
    const int*   bidx  = (const int*)d_in[3];
    const float* eps1  = (const float*)d_in[4];
    const float* eps2  = (const float*)d_in[5];
    const float* uw1 = (const float*)d_in[6];
    const float* ub1 = (const float*)d_in[7];
    const float* ug1 = (const float*)d_in[8];
    const float* ube1= (const float*)d_in[9];
    const float* uw2 = (const float*)d_in[10];
    const float* ub2 = (const float*)d_in[11];
    const float* ug2 = (const float*)d_in[12];
    const float* ube2= (const float*)d_in[13];
    const float* bw1 = (const float*)d_in[14];
    const float* bb1 = (const float*)d_in[15];
    const float* bg1 = (const float*)d_in[16];
    const float* bbe1= (const float*)d_in[17];
    const float* bw2 = (const float*)d_in[18];
    const float* bb2 = (const float*)d_in[19];
    const float* bg2 = (const float*)d_in[20];
    const float* bbe2= (const float*)d_in[21];
    const float* cw  = (const float*)d_in[22];
    const float* cb  = (const float*)d_in[23];
    const float* cg  = (const float*)d_in[24];
    const float* cbe = (const float*)d_in[25];
    float* out = (float*)d_out;

    int N  = in_sizes[0] / HDIM;
    int EU = in_sizes[2] / 2;
    int EB = in_sizes[3] / 2;

    float *aggu, *aggb, *y1u, *y1b, *y2, *stats;
    float *sc1u, *sh1u, *sc1b, *sh1b, *sc2, *sh2, *sc3, *sh3;
    cudaGetSymbolAddress((void**)&aggu,  g_aggu);
    cudaGetSymbolAddress((void**)&aggb,  g_aggb);
    cudaGetSymbolAddress((void**)&y1u,   g_y1u);
    cudaGetSymbolAddress((void**)&y1b,   g_y1b);
    cudaGetSymbolAddress((void**)&y2,    g_y2);
    cudaGetSymbolAddress((void**)&stats, g_stats);
    cudaGetSymbolAddress((void**)&sc1u,  g_sc1u);
    cudaGetSymbolAddress((void**)&sh1u,  g_sh1u);
    cudaGetSymbolAddress((void**)&sc1b,  g_sc1b);
    cudaGetSymbolAddress((void**)&sh1b,  g_sh1b);
    cudaGetSymbolAddress((void**)&sc2,   g_sc2);
    cudaGetSymbolAddress((void**)&sh2,   g_sh2);
    cudaGetSymbolAddress((void**)&sc3,   g_sc3);
    cudaGetSymbolAddress((void**)&sh3,   g_sh3);

    float invN = 1.0f / (float)N;
    int total4 = (N * HDIM) / 4;
    int gb = (N + 127) / 128;

    // Phase 0: init aggregates + zero stats
    init_kernel<<<592, 256>>>(x, eps1, eps2, aggu, aggb, stats, total4);

    // Phase 1: scatter-adds (vectorized RED)
    // up:       agg_up[up_index[0][e]]       += x[up_index[1][e]]
    // boundary: agg_b [boundary_index[1][e]] += battr[boundary_index[0][e]]
    scatter_kernel<<<8192, 256>>>(x,     upidx,     upidx + EU, EU, aggu);
    scatter_kernel<<<2048, 256>>>(battr, bidx + EB, bidx,       EB, aggb);

    // Phase 2: layer-1 GEMMs (+ BN stats)
    gemm_bn<64, false><<<gb, 256>>>(aggu, uw1, ub1, nullptr, nullptr, y1u, 64, stats + 0,   N);
    gemm_bn<64, false><<<gb, 256>>>(aggb, bw1, bb1, nullptr, nullptr, y1b, 64, stats + 128, N);
    coeffs_kernel<<<1, 64>>>(stats + 0,   ug1, ube1, sc1u, sh1u, invN);
    coeffs_kernel<<<1, 64>>>(stats + 128, bg1, bbe1, sc1b, sh1b, invN);

    // Phase 3: layer-2 GEMMs with fused BN+ReLU on input; outputs interleave
    // into y2[N][128] (u -> cols 0..63, b -> cols 64..127)
    gemm_bn<64, true><<<gb, 256>>>(y1u, uw2, ub2, sc1u, sh1u, y2,      128, stats + 256, N);
    gemm_bn<64, true><<<gb, 256>>>(y1b, bw2, bb2, sc1b, sh1b, y2 + 64, 128, stats + 384, N);
    coeffs_kernel<<<1, 64>>>(stats + 256, ug2, ube2, sc2,      sh2,      invN);
    coeffs_kernel<<<1, 64>>>(stats + 384, bg2, bbe2, sc2 + 64, sh2 + 64, invN);

    // Phase 4: combine GEMM (K=128) with fused BN+ReLU on input, write to out
    gemm_bn<128, true><<<gb, 256>>>(y2, cw, cb, sc2, sh2, out, 64, stats + 512, N);
    coeffs_kernel<<<1, 64>>>(stats + 512, cg, cbe, sc3, sh3, invN);

    // Phase 5: final BN+ReLU in place on out
    bnrelu_kernel<<<592, 256>>>(out, sc3, sh3, total4);
}

// round 4
// speedup vs baseline: 1.2414x; 1.0795x over previous
#include <cuda_runtime.h>
#include <cstddef>

#define HDIM 64
#define NMAX 100352

// ---------------- scratch (static device globals; no allocation allowed) ----
__device__ float g_aggu[(size_t)NMAX * HDIM];
__device__ float g_aggb[(size_t)NMAX * HDIM];
__device__ float g_y1u[(size_t)NMAX * HDIM];
__device__ float g_y1b[(size_t)NMAX * HDIM];
__device__ float g_y2[(size_t)NMAX * 2 * HDIM];
__device__ float g_stats[5 * 128];     // per BN: [0..63]=sum, [64..127]=sumsq
__device__ float g_sc1u[64], g_sh1u[64];
__device__ float g_sc1b[64], g_sh1b[64];
__device__ float g_sc2[128], g_sh2[128];
__device__ float g_sc3[64],  g_sh3[64];

// ---------------- init: agg = (1+eps)*x, zero stats ------------------------
__global__ void init_kernel(const float* __restrict__ x,
                            const float* __restrict__ eps1,
                            const float* __restrict__ eps2,
                            float* __restrict__ aggu,
                            float* __restrict__ aggb,
                            float* __restrict__ stats,
                            int total4)
{
    int i = blockIdx.x * blockDim.x + threadIdx.x;
    if (i < 5 * 128) stats[i] = 0.0f;
    float a = 1.0f + __ldg(eps1);
    float b = 1.0f + __ldg(eps2);
    const float4* x4 = (const float4*)x;
    float4* u4 = (float4*)aggu;
    float4* b4 = (float4*)aggb;
    int stride = gridDim.x * blockDim.x;
    for (int t = i; t < total4; t += stride) {
        float4 v = x4[t];
        float4 r;
        r.x = a * v.x; r.y = a * v.y; r.z = a * v.z; r.w = a * v.w;
        u4[t] = r;
        float4 s;
        s.x = b * v.x; s.y = b * v.y; s.z = b * v.z; s.w = b * v.w;
        b4[t] = s;
    }
}

// ---------------- scatter-add: agg[dst[e]] += feat[src[e]] ------------------
// Work item = one 16-byte chunk of one edge. 16 chunks per edge (H=64).
__global__ void scatter_kernel(const float* __restrict__ feat,
                               const int* __restrict__ dst_idx,
                               const int* __restrict__ src_idx,
                               int E,
                               float* __restrict__ agg)
{
    long t = blockIdx.x * (long)blockDim.x + threadIdx.x;
    long stride = gridDim.x * (long)blockDim.x;
    long total = (long)E * 16;
    for (long i = t; i < total; i += stride) {
        int e = (int)(i >> 4);
        int c = (int)(i & 15);
        int dst = __ldg(&dst_idx[e]);
        int src = __ldg(&src_idx[e]);
        float4 v = *(const float4*)(feat + ((size_t)src << 6) + c * 4);
        float* p = agg + ((size_t)dst << 6) + c * 4;
        asm volatile("red.global.add.v4.f32 [%0], {%1,%2,%3,%4};"
                     :: "l"(p), "f"(v.x), "f"(v.y), "f"(v.z), "f"(v.w)
                     : "memory");
    }
}

// ---------------- f32x2 helpers --------------------------------------------
__device__ __forceinline__ unsigned long long dup2(float v) {
    unsigned long long r;
    asm("mov.b64 %0, {%1, %1};" : "=l"(r) : "r"(__float_as_uint(v)));
    return r;
}
__device__ __forceinline__ void ffma2(unsigned long long& d,
                                      unsigned long long a,
                                      unsigned long long b) {
    asm("fma.rn.f32x2 %0, %1, %2, %0;" : "+l"(d) : "l"(a), "l"(b));
}
__device__ __forceinline__ float2 unpk(unsigned long long v) {
    unsigned int lo, hi;
    asm("mov.b64 {%0, %1}, %2;" : "=r"(lo), "=r"(hi) : "l"(v));
    return make_float2(__uint_as_float(lo), __uint_as_float(hi));
}

// ---------------- GEMM + bias + (fused input BN-affine+ReLU) + BN stats -----
// Y[i][j] = sum_k act(A[i][k]) * W[k][j] + bias[j]
// Dual operand sets selected by blockIdx.y (merged u/b launches).
// Tile: 128 rows x 64 cols, 256 threads, 4x8 microtile, inner math in f32x2.
struct GArg {
    const float* A;
    const float* W;
    const float* bias;
    const float* inScale;
    const float* inShift;
    float* Y;
    float* stats;
};

template <int K, bool AFF>
__global__ __launch_bounds__(256, 4)
void gemm_bn(GArg ga, GArg gb, int ldY, int N)
{
    __shared__ float As[32][132];   // transposed A chunk: As[k][row]
    __shared__ float Ws[32][64];    // W chunk: Ws[k][col]
    __shared__ float sSc[AFF ? K : 1];
    __shared__ float sSh[AFF ? K : 1];

    const GArg g = (blockIdx.y == 0) ? ga : gb;

    const int tid = threadIdx.x;          // 0..255
    const int tx  = tid & 31;             // row group (4 rows each), 0..31
    const int ty  = tid >> 5;             // col group (8 cols each), 0..7
    const int rbase = blockIdx.x * 128;

    if (AFF) {
        if (tid < K) {
            sSc[tid] = g.inScale[tid];
            sSh[tid] = g.inShift[tid];
        }
        __syncthreads();
    }

    // acc[i][p] packs cols (ty*8 + 2p, ty*8 + 2p + 1) for row (tx*4 + i)
    unsigned long long acc[4][4];
#pragma unroll
    for (int i = 0; i < 4; i++)
#pragma unroll
        for (int p = 0; p < 4; p++) acc[i][p] = 0ull;

#pragma unroll
    for (int kc = 0; kc < K; kc += 32) {
        // --- load A chunk (128 rows x 32 cols), transform, transpose-store
#pragma unroll
        for (int it = 0; it < 4; it++) {
            int lin = it * 256 + tid;     // 1024 float4 slots
            int r   = lin >> 3;           // 8 float4 per row
            int c4  = lin & 7;
            int gr  = rbase + r;
            float4 v = make_float4(0.f, 0.f, 0.f, 0.f);
            if (gr < N)
                v = *(const float4*)&g.A[(size_t)gr * K + kc + c4 * 4];
            if (AFF) {
                int c = kc + c4 * 4;
                float4 s = *(const float4*)&sSc[c];
                float4 h = *(const float4*)&sSh[c];
                v.x = fmaxf(v.x * s.x + h.x, 0.f);
                v.y = fmaxf(v.y * s.y + h.y, 0.f);
                v.z = fmaxf(v.z * s.z + h.z, 0.f);
                v.w = fmaxf(v.w * s.w + h.w, 0.f);
            }
            As[c4 * 4 + 0][r] = v.x;
            As[c4 * 4 + 1][r] = v.y;
            As[c4 * 4 + 2][r] = v.z;
            As[c4 * 4 + 3][r] = v.w;
        }
        // --- load W chunk (32 rows x 64 cols)
#pragma unroll
        for (int it = 0; it < 2; it++) {
            int lin = it * 256 + tid;     // 512 float4
            int r   = lin >> 4;           // 16 float4 per row
            int c4  = lin & 15;
            *(float4*)&Ws[r][c4 * 4] = *(const float4*)&g.W[(size_t)(kc + r) * 64 + c4 * 4];
        }
        __syncthreads();

        // --- compute (f32x2 packed)
#pragma unroll
        for (int k = 0; k < 32; k++) {
            float4 av = *(const float4*)&As[k][tx * 4];
            ulonglong2 w03 = *(const ulonglong2*)&Ws[k][ty * 8];
            ulonglong2 w47 = *(const ulonglong2*)&Ws[k][ty * 8 + 4];
            unsigned long long wp[4] = { w03.x, w03.y, w47.x, w47.y };
            unsigned long long ad[4] = { dup2(av.x), dup2(av.y), dup2(av.z), dup2(av.w) };
#pragma unroll
            for (int i = 0; i < 4; i++)
#pragma unroll
                for (int p = 0; p < 4; p++)
                    ffma2(acc[i][p], ad[i], wp[p]);
        }
        if (kc + 32 < K) __syncthreads();
    }

    // --- epilogue: bias, store, per-warp stats reduction
    float b[8];
    *(float4*)&b[0] = *(const float4*)&g.bias[ty * 8];
    *(float4*)&b[4] = *(const float4*)&g.bias[ty * 8 + 4];

    float psum[8], psq[8];
#pragma unroll
    for (int j = 0; j < 8; j++) { psum[j] = 0.f; psq[j] = 0.f; }

#pragma unroll
    for (int i = 0; i < 4; i++) {
        int gr = rbase + tx * 4 + i;
        if (gr < N) {
            float v[8];
#pragma unroll
            for (int p = 0; p < 4; p++) {
                float2 t = unpk(acc[i][p]);
                v[2 * p + 0] = t.x + b[2 * p + 0];
                v[2 * p + 1] = t.y + b[2 * p + 1];
            }
#pragma unroll
            for (int j = 0; j < 8; j++) {
                psum[j] += v[j];
                psq[j]  += v[j] * v[j];
            }
            float* yp = &g.Y[(size_t)gr * ldY + ty * 8];
            *(float4*)&yp[0] = *(float4*)&v[0];
            *(float4*)&yp[4] = *(float4*)&v[4];
        }
    }
    // warp-wide reduce (all lanes participate; OOB rows contributed 0)
#pragma unroll
    for (int j = 0; j < 8; j++) {
#pragma unroll
        for (int o = 16; o > 0; o >>= 1) {
            psum[j] += __shfl_xor_sync(0xFFFFFFFFu, psum[j], o);
            psq[j]  += __shfl_xor_sync(0xFFFFFFFFu, psq[j],  o);
        }
    }
    if (tx == 0) {
#pragma unroll
        for (int j = 0; j < 8; j++) {
            atomicAdd(&g.stats[ty * 8 + j], psum[j]);
            atomicAdd(&g.stats[64 + ty * 8 + j], psq[j]);
        }
    }
}

// ---------------- BN coefficients: scale = g*rstd, shift = be - mean*scale --
__global__ void coeffs_kernel(const float* __restrict__ stats,
                              const float* __restrict__ g,
                              const float* __restrict__ be,
                              float* __restrict__ scale,
                              float* __restrict__ shift,
                              float invN)
{
    int j = threadIdx.x;
    if (j < 64) {
        float mean = stats[j] * invN;
        float var  = stats[64 + j] * invN - mean * mean;
        float rstd = rsqrtf(var + 1e-5f);
        float s = g[j] * rstd;
        scale[j] = s;
        shift[j] = be[j] - mean * s;
    }
}

// ---------------- final in-place BN + ReLU ---------------------------------
__global__ void bnrelu_kernel(float* __restrict__ Y,
                              const float* __restrict__ scale,
                              const float* __restrict__ shift,
                              int total4)
{
    int i = blockIdx.x * blockDim.x + threadIdx.x;
    int stride = gridDim.x * blockDim.x;
    float4* y4 = (float4*)Y;
    for (int t = i; t < total4; t += stride) {
        int c = (t * 4) & 63;
        float4 v = y4[t];
        float4 s = *(const float4*)&scale[c];
        float4 h = *(const float4*)&shift[c];
        v.x = fmaxf(v.x * s.x + h.x, 0.f);
        v.y = fmaxf(v.y * s.y + h.y, 0.f);
        v.z = fmaxf(v.z * s.z + h.z, 0.f);
        v.w = fmaxf(v.w * s.w + h.w, 0.f);
        y4[t] = v;
    }
}

// ---------------- launch ----------------------------------------------------
extern "C" void kernel_launch(void* const* d_in, const int* in_sizes, int n_in,
                              void* d_out, int out_size)
{
    const float* x     = (const float*)d_in[0];
    const float* battr = (const float*)d_in[1];
    const int*   upidx = (const int*)d_in[2];
    const int*   bidx  = (const int*)d_in[3];
    const float* eps1  = (const float*)d_in[4];
    const float* eps2  = (const float*)d_in[5];
    const float* uw1 = (const float*)d_in[6];
    const float* ub1 = (const float*)d_in[7];
    const float* ug1 = (const float*)d_in[8];
    const float* ube1= (const float*)d_in[9];
    const float* uw2 = (const float*)d_in[10];
    const float* ub2 = (const float*)d_in[11];
    const float* ug2 = (const float*)d_in[12];
    const float* ube2= (const float*)d_in[13];
    const float* bw1 = (const float*)d_in[14];
    const float* bb1 = (const float*)d_in[15];
    const float* bg1 = (const float*)d_in[16];
    const float* bbe1= (const float*)d_in[17];
    const float* bw2 = (const float*)d_in[18];
    const float* bb2 = (const float*)d_in[19];
    const float* bg2 = (const float*)d_in[20];
    const float* bbe2= (const float*)d_in[21];
    const float* cw  = (const float*)d_in[22];
    const float* cb  = (const float*)d_in[23];
    const float* cg  = (const float*)d_in[24];
    const float* cbe = (const float*)d_in[25];
    float* out = (float*)d_out;

    int N  = in_sizes[0] / HDIM;
    int EU = in_sizes[2] / 2;
    int EB = in_sizes[3] / 2;

    float *aggu, *aggb, *y1u, *y1b, *y2, *stats;
    float *sc1u, *sh1u, *sc1b, *sh1b, *sc2, *sh2, *sc3, *sh3;
    cudaGetSymbolAddress((void**)&aggu,  g_aggu);
    cudaGetSymbolAddress((void**)&aggb,  g_aggb);
    cudaGetSymbolAddress((void**)&y1u,   g_y1u);
    cudaGetSymbolAddress((void**)&y1b,   g_y1b);
    cudaGetSymbolAddress((void**)&y2,    g_y2);
    cudaGetSymbolAddress((void**)&stats, g_stats);
    cudaGetSymbolAddress((void**)&sc1u,  g_sc1u);
    cudaGetSymbolAddress((void**)&sh1u,  g_sh1u);
    cudaGetSymbolAddress((void**)&sc1b,  g_sc1b);
    cudaGetSymbolAddress((void**)&sh1b,  g_sh1b);
    cudaGetSymbolAddress((void**)&sc2,   g_sc2);
    cudaGetSymbolAddress((void**)&sh2,   g_sh2);
    cudaGetSymbolAddress((void**)&sc3,   g_sc3);
    cudaGetSymbolAddress((void**)&sh3,   g_sh3);

    float invN = 1.0f / (float)N;
    int total4 = (N * HDIM) / 4;
    int gb = (N + 127) / 128;

    // Phase 0: init aggregates + zero stats
    init_kernel<<<592, 256>>>(x, eps1, eps2, aggu, aggb, stats, total4);

    // Phase 1: scatter-adds (vectorized RED)
    scatter_kernel<<<8192, 256>>>(x,     upidx,     upidx + EU, EU, aggu);
    scatter_kernel<<<2048, 256>>>(battr, bidx + EB, bidx,       EB, aggb);

    // Phase 2: layer-1 GEMMs (merged dual launch, + BN stats)
    {
        GArg gu = { aggu, uw1, ub1, nullptr, nullptr, y1u, stats + 0 };
        GArg gv = { aggb, bw1, bb1, nullptr, nullptr, y1b, stats + 128 };
        gemm_bn<64, false><<<dim3(gb, 2), 256>>>(gu, gv, 64, N);
    }
    coeffs_kernel<<<1, 64>>>(stats + 0,   ug1, ube1, sc1u, sh1u, invN);
    coeffs_kernel<<<1, 64>>>(stats + 128, bg1, bbe1, sc1b, sh1b, invN);

    // Phase 3: layer-2 GEMMs with fused BN+ReLU on input; outputs interleave
    // into y2[N][128] (u -> cols 0..63, b -> cols 64..127)
    {
        GArg gu = { y1u, uw2, ub2, sc1u, sh1u, y2,      stats + 256 };
        GArg gv = { y1b, bw2, bb2, sc1b, sh1b, y2 + 64, stats + 384 };
        gemm_bn<64, true><<<dim3(gb, 2), 256>>>(gu, gv, 128, N);
    }
    coeffs_kernel<<<1, 64>>>(stats + 256, ug2, ube2, sc2,      sh2,      invN);
    coeffs_kernel<<<1, 64>>>(stats + 384, bg2, bbe2, sc2 + 64, sh2 + 64, invN);

    // Phase 4: combine GEMM (K=128) with fused BN+ReLU on input, write to out
    {
        GArg gc = { y2, cw, cb, sc2, sh2, out, stats + 512 };
        gemm_bn<128, true><<<dim3(gb, 1), 256>>>(gc, gc, 64, N);
    }
    coeffs_kernel<<<1, 64>>>(stats + 512, cg, cbe, sc3, sh3, invN);

    // Phase 5: final BN+ReLU in place on out
    bnrelu_kernel<<<592, 256>>>(out, sc3, sh3, total4);
}

// round 5
// speedup vs baseline: 1.4286x; 1.1508x over previous
#include <cuda_runtime.h>
#include <cstddef>

#define HDIM 64
#define NMAX 100352

// ---------------- scratch (static device globals; no allocation allowed) ----
__device__ float g_aggu[(size_t)NMAX * HDIM];
__device__ float g_aggb[(size_t)NMAX * HDIM];
__device__ float g_y1u[(size_t)NMAX * HDIM];
__device__ float g_y1b[(size_t)NMAX * HDIM];
__device__ float g_y2[(size_t)NMAX * 2 * HDIM];
__device__ float g_stats[5 * 128];     // per BN: [0..63]=sum, [64..127]=sumsq
__device__ float g_sc1u[64], g_sh1u[64];
__device__ float g_sc1b[64], g_sh1b[64];
__device__ float g_sc2[128], g_sh2[128];
__device__ float g_sc3[64],  g_sh3[64];

// ---------------- init: agg = (1+eps)*x, zero stats ------------------------
__global__ void init_kernel(const float* __restrict__ x,
                            const float* __restrict__ eps1,
                            const float* __restrict__ eps2,
                            float* __restrict__ aggu,
                            float* __restrict__ aggb,
                            float* __restrict__ stats,
                            int total4)
{
    int i = blockIdx.x * blockDim.x + threadIdx.x;
    if (i < 5 * 128) stats[i] = 0.0f;
    float a = 1.0f + __ldg(eps1);
    float b = 1.0f + __ldg(eps2);
    const float4* x4 = (const float4*)x;
    float4* u4 = (float4*)aggu;
    float4* b4 = (float4*)aggb;
    int stride = gridDim.x * blockDim.x;
    for (int t = i; t < total4; t += stride) {
        float4 v = x4[t];
        float4 r;
        r.x = a * v.x; r.y = a * v.y; r.z = a * v.z; r.w = a * v.w;
        u4[t] = r;
        float4 s;
        s.x = b * v.x; s.y = b * v.y; s.z = b * v.z; s.w = b * v.w;
        b4[t] = s;
    }
}

// ---------------- merged scatter-add for both edge sets ---------------------
// Work item = one 16-byte chunk of one edge. 16 chunks per edge (H=64).
__global__ void scatter2_kernel(const float* __restrict__ featu,
                                const int* __restrict__ du,
                                const int* __restrict__ su, int EU,
                                const float* __restrict__ featb,
                                const int* __restrict__ db,
                                const int* __restrict__ sb, int EB,
                                float* __restrict__ aggu,
                                float* __restrict__ aggb)
{
    long t = blockIdx.x * (long)blockDim.x + threadIdx.x;
    long stride = gridDim.x * (long)blockDim.x;
    long total = (long)(EU + EB) * 16;
    for (long i = t; i < total; i += stride) {
        int e = (int)(i >> 4);
        int c = (int)(i & 15);
        const float* feat;
        float* agg;
        int dst, src;
        if (e < EU) {
            dst = __ldg(&du[e]);
            src = __ldg(&su[e]);
            feat = featu; agg = aggu;
        } else {
            int eb = e - EU;
            dst = __ldg(&db[eb]);
            src = __ldg(&sb[eb]);
            feat = featb; agg = aggb;
        }
        float4 v = *(const float4*)(feat + ((size_t)src << 6) + c * 4);
        float* p = agg + ((size_t)dst << 6) + c * 4;
        asm volatile("red.global.add.v4.f32 [%0], {%1,%2,%3,%4};"
                     :: "l"(p), "f"(v.x), "f"(v.y), "f"(v.z), "f"(v.w)
                     : "memory");
    }
}

// ---------------- f32x2 helpers --------------------------------------------
__device__ __forceinline__ unsigned long long dup2(float v) {
    unsigned long long r;
    asm("mov.b64 %0, {%1, %1};" : "=l"(r) : "r"(__float_as_uint(v)));
    return r;
}
__device__ __forceinline__ void ffma2(unsigned long long& d,
                                      unsigned long long a,
                                      unsigned long long b) {
    asm("fma.rn.f32x2 %0, %1, %2, %0;" : "+l"(d) : "l"(a), "l"(b));
}
__device__ __forceinline__ float2 unpk(unsigned long long v) {
    unsigned int lo, hi;
    asm("mov.b64 {%0, %1}, %2;" : "=r"(lo), "=r"(hi) : "l"(v));
    return make_float2(__uint_as_float(lo), __uint_as_float(hi));
}

// ---------------- GEMM + bias + (fused input BN-affine+ReLU) + BN stats -----
// Y[i][j] = sum_k act(A[i][k]) * W[k][j] + bias[j]
// Dual operand sets selected by blockIdx.y (merged u/b launches).
// Tile: 256 rows x 64 cols, 256 threads, 8x8 microtile (two 128-row halves),
// inner math in packed f32x2 (cols paired).
struct GArg {
    const float* A;
    const float* W;
    const float* bias;
    const float* inScale;
    const float* inShift;
    float* Y;
    float* stats;
};

template <int K, bool AFF>
__global__ __launch_bounds__(256, 2)
void gemm_bn(GArg ga, GArg gb, int ldY, int N)
{
    __shared__ float As[32][260];   // transposed A chunk: As[k][row], stride 260 (16B-aligned, low-conflict)
    __shared__ float Ws[32][64];    // W chunk: Ws[k][col]
    __shared__ float sSc[AFF ? K : 1];
    __shared__ float sSh[AFF ? K : 1];

    const GArg g = (blockIdx.y == 0) ? ga : gb;

    const int tid  = threadIdx.x;         // 0..255
    const int lane = tid & 31;            // 4 rows per half
    const int wy   = tid >> 5;            // col group (8 cols), 0..7
    const int rbase = blockIdx.x * 256;

    if (AFF) {
        if (tid < K) {
            sSc[tid] = g.inScale[tid];
            sSh[tid] = g.inShift[tid];
        }
        __syncthreads();
    }

    // acc[i][p]: row i (i<4 -> half0 rows lane*4+i; i>=4 -> half1 rows 128+lane*4+i-4),
    // cols (wy*8 + 2p, wy*8 + 2p + 1)
    unsigned long long acc[8][4];
#pragma unroll
    for (int i = 0; i < 8; i++)
#pragma unroll
        for (int p = 0; p < 4; p++) acc[i][p] = 0ull;

#pragma unroll
    for (int kc = 0; kc < K; kc += 32) {
        // --- load A chunk (256 rows x 32 cols), transform, transpose-store
#pragma unroll
        for (int it = 0; it < 8; it++) {
            int lin = it * 256 + tid;     // 2048 float4 slots
            int r   = lin >> 3;           // 8 float4 per row, r = 0..255
            int c4  = lin & 7;
            int gr  = rbase + r;
            float4 v = make_float4(0.f, 0.f, 0.f, 0.f);
            if (gr < N)
                v = *(const float4*)&g.A[(size_t)gr * K + kc + c4 * 4];
            if (AFF) {
                int c = kc + c4 * 4;
                float4 s = *(const float4*)&sSc[c];
                float4 h = *(const float4*)&sSh[c];
                v.x = fmaxf(v.x * s.x + h.x, 0.f);
                v.y = fmaxf(v.y * s.y + h.y, 0.f);
                v.z = fmaxf(v.z * s.z + h.z, 0.f);
                v.w = fmaxf(v.w * s.w + h.w, 0.f);
            }
            As[c4 * 4 + 0][r] = v.x;
            As[c4 * 4 + 1][r] = v.y;
            As[c4 * 4 + 2][r] = v.z;
            As[c4 * 4 + 3][r] = v.w;
        }
        // --- load W chunk (32 rows x 64 cols)
#pragma unroll
        for (int it = 0; it < 2; it++) {
            int lin = it * 256 + tid;     // 512 float4
            int r   = lin >> 4;           // 16 float4 per row
            int c4  = lin & 15;
            *(float4*)&Ws[r][c4 * 4] = *(const float4*)&g.W[(size_t)(kc + r) * 64 + c4 * 4];
        }
        __syncthreads();

        // --- compute (f32x2 packed cols, 8 rows per thread)
#pragma unroll
        for (int k = 0; k < 32; k++) {
            float4 alo = *(const float4*)&As[k][lane * 4];        // conflict-free (contiguous warp)
            float4 ahi = *(const float4*)&As[k][128 + lane * 4];  // conflict-free
            ulonglong2 w03 = *(const ulonglong2*)&Ws[k][wy * 8];  // broadcast
            ulonglong2 w47 = *(const ulonglong2*)&Ws[k][wy * 8 + 4];
            unsigned long long wp[4] = { w03.x, w03.y, w47.x, w47.y };
            unsigned long long ad[8] = {
                dup2(alo.x), dup2(alo.y), dup2(alo.z), dup2(alo.w),
                dup2(ahi.x), dup2(ahi.y), dup2(ahi.z), dup2(ahi.w)
            };
#pragma unroll
            for (int i = 0; i < 8; i++)
#pragma unroll
                for (int p = 0; p < 4; p++)
                    ffma2(acc[i][p], ad[i], wp[p]);
        }
        if (kc + 32 < K) __syncthreads();
    }

    // --- epilogue: bias, store, per-warp stats reduction
    float b[8];
    *(float4*)&b[0] = *(const float4*)&g.bias[wy * 8];
    *(float4*)&b[4] = *(const float4*)&g.bias[wy * 8 + 4];

    float psum[8], psq[8];
#pragma unroll
    for (int j = 0; j < 8; j++) { psum[j] = 0.f; psq[j] = 0.f; }

#pragma unroll
    for (int i = 0; i < 8; i++) {
        int gr = rbase + ((i < 4) ? (lane * 4 + i) : (128 + lane * 4 + i - 4));
        if (gr < N) {
            float v[8];
#pragma unroll
            for (int p = 0; p < 4; p++) {
                float2 t = unpk(acc[i][p]);
                v[2 * p + 0] = t.x + b[2 * p + 0];
                v[2 * p + 1] = t.y + b[2 * p + 1];
            }
#pragma unroll
            for (int j = 0; j < 8; j++) {
                psum[j] += v[j];
                psq[j]  += v[j] * v[j];
            }
            float* yp = &g.Y[(size_t)gr * ldY + wy * 8];
            *(float4*)&yp[0] = *(float4*)&v[0];
            *(float4*)&yp[4] = *(float4*)&v[4];
        }
    }
    // warp-wide reduce (all lanes participate; OOB rows contributed 0)
#pragma unroll
    for (int j = 0; j < 8; j++) {
#pragma unroll
        for (int o = 16; o > 0; o >>= 1) {
            psum[j] += __shfl_xor_sync(0xFFFFFFFFu, psum[j], o);
            psq[j]  += __shfl_xor_sync(0xFFFFFFFFu, psq[j],  o);
        }
    }
    if (lane == 0) {
#pragma unroll
        for (int j = 0; j < 8; j++) {
            atomicAdd(&g.stats[wy * 8 + j], psum[j]);
            atomicAdd(&g.stats[64 + wy * 8 + j], psq[j]);
        }
    }
}

// ---------------- BN coefficients: scale = g*rstd, shift = be - mean*scale --
__global__ void coeffs_kernel(const float* __restrict__ stats,
                              const float* __restrict__ g,
                              const float* __restrict__ be,
                              float* __restrict__ scale,
                              float* __restrict__ shift,
                              float invN)
{
    int j = threadIdx.x;
    if (j < 64) {
        float mean = stats[j] * invN;
        float var  = stats[64 + j] * invN - mean * mean;
        float rstd = rsqrtf(var + 1e-5f);
        float s = g[j] * rstd;
        scale[j] = s;
        shift[j] = be[j] - mean * s;
    }
}

// ---------------- final in-place BN + ReLU ---------------------------------
__global__ void bnrelu_kernel(float* __restrict__ Y,
                              const float* __restrict__ scale,
                              const float* __restrict__ shift,
                              int total4)
{
    int i = blockIdx.x * blockDim.x + threadIdx.x;
    int stride = gridDim.x * blockDim.x;
    float4* y4 = (float4*)Y;
    for (int t = i; t < total4; t += stride) {
        int c = (t * 4) & 63;
        float4 v = y4[t];
        float4 s = *(const float4*)&scale[c];
        float4 h = *(const float4*)&shift[c];
        v.x = fmaxf(v.x * s.x + h.x, 0.f);
        v.y = fmaxf(v.y * s.y + h.y, 0.f);
        v.z = fmaxf(v.z * s.z + h.z, 0.f);
        v.w = fmaxf(v.w * s.w + h.w, 0.f);
        y4[t] = v;
    }
}

// ---------------- launch ----------------------------------------------------
extern "C" void kernel_launch(void* const* d_in, const int* in_sizes, int n_in,
                              void* d_out, int out_size)
{
    const float* x     = (const float*)d_in[0];
    const float* battr = (const float*)d_in[1];
    const int*   upidx = (const int*)d_in[2];
    const int*   bidx  = (const int*)d_in[3];
    const float* eps1  = (const float*)d_in[4];
    const float* eps2  = (const float*)d_in[5];
    const float* uw1 = (const float*)d_in[6];
    const float* ub1 = (const float*)d_in[7];
    const float* ug1 = (const float*)d_in[8];
    const float* ube1= (const float*)d_in[9];
    const float* uw2 = (const float*)d_in[10];
    const float* ub2 = (const float*)d_in[11];
    const float* ug2 = (const float*)d_in[12];
    const float* ube2= (const float*)d_in[13];
    const float* bw1 = (const float*)d_in[14];
    const float* bb1 = (const float*)d_in[15];
    const float* bg1 = (const float*)d_in[16];
    const float* bbe1= (const float*)d_in[17];
    const float* bw2 = (const float*)d_in[18];
    const float* bb2 = (const float*)d_in[19];
    const float* bg2 = (const float*)d_in[20];
    const float* bbe2= (const float*)d_in[21];
    const float* cw  = (const float*)d_in[22];
    const float* cb  = (const float*)d_in[23];
    const float* cg  = (const float*)d_in[24];
    const float* cbe = (const float*)d_in[25];
    float* out = (float*)d_out;

    int N  = in_sizes[0] / HDIM;
    int EU = in_sizes[2] / 2;
    int EB = in_sizes[3] / 2;

    float *aggu, *aggb, *y1u, *y1b, *y2, *stats;
    float *sc1u, *sh1u, *sc1b, *sh1b, *sc2, *sh2, *sc3, *sh3;
    cudaGetSymbolAddress((void**)&aggu,  g_aggu);
    cudaGetSymbolAddress((void**)&aggb,  g_aggb);
    cudaGetSymbolAddress((void**)&y1u,   g_y1u);
    cudaGetSymbolAddress((void**)&y1b,   g_y1b);
    cudaGetSymbolAddress((void**)&y2,    g_y2);
    cudaGetSymbolAddress((void**)&stats, g_stats);
    cudaGetSymbolAddress((void**)&sc1u,  g_sc1u);
    cudaGetSymbolAddress((void**)&sh1u,  g_sh1u);
    cudaGetSymbolAddress((void**)&sc1b,  g_sc1b);
    cudaGetSymbolAddress((void**)&sh1b,  g_sh1b);
    cudaGetSymbolAddress((void**)&sc2,   g_sc2);
    cudaGetSymbolAddress((void**)&sh2,   g_sh2);
    cudaGetSymbolAddress((void**)&sc3,   g_sc3);
    cudaGetSymbolAddress((void**)&sh3,   g_sh3);

    float invN = 1.0f / (float)N;
    int total4 = (N * HDIM) / 4;
    int gb = (N + 255) / 256;

    // Phase 0: init aggregates + zero stats
    init_kernel<<<592, 256>>>(x, eps1, eps2, aggu, aggb, stats, total4);

    // Phase 1: merged scatter-adds (vectorized RED)
    // up:       agg_up[up_index[0][e]]       += x[up_index[1][e]]
    // boundary: agg_b [boundary_index[1][e]] += battr[boundary_index[0][e]]
    scatter2_kernel<<<10240, 256>>>(x, upidx, upidx + EU, EU,
                                    battr, bidx + EB, bidx, EB,
                                    aggu, aggb);

    // Phase 2: layer-1 GEMMs (merged dual launch, + BN stats)
    {
        GArg gu = { aggu, uw1, ub1, nullptr, nullptr, y1u, stats + 0 };
        GArg gv = { aggb, bw1, bb1, nullptr, nullptr, y1b, stats + 128 };
        gemm_bn<64, false><<<dim3(gb, 2), 256>>>(gu, gv, 64, N);
    }
    coeffs_kernel<<<1, 64>>>(stats + 0,   ug1, ube1, sc1u, sh1u, invN);
    coeffs_kernel<<<1, 64>>>(stats + 128, bg1, bbe1, sc1b, sh1b, invN);

    // Phase 3: layer-2 GEMMs with fused BN+ReLU on input; outputs interleave
    // into y2[N][128] (u -> cols 0..63, b -> cols 64..127)
    {
        GArg gu = { y1u, uw2, ub2, sc1u, sh1u, y2,      stats + 256 };
        GArg gv = { y1b, bw2, bb2, sc1b, sh1b, y2 + 64, stats + 384 };
        gemm_bn<64, true><<<dim3(gb, 2), 256>>>(gu, gv, 128, N);
    }
    coeffs_kernel<<<1, 64>>>(stats + 256, ug2, ube2, sc2,      sh2,      invN);
    coeffs_kernel<<<1, 64>>>(stats + 384, bg2, bbe2, sc2 + 64, sh2 + 64, invN);

    // Phase 4: combine GEMM (K=128) with fused BN+ReLU on input, write to out
    {
        GArg gc = { y2, cw, cb, sc2, sh2, out, stats + 512 };
        gemm_bn<128, true><<<dim3(gb, 1), 256>>>(gc, gc, 64, N);
    }
    coeffs_kernel<<<1, 64>>>(stats + 512, cg, cbe, sc3, sh3, invN);

    // Phase 5: final BN+ReLU in place on out
    bnrelu_kernel<<<592, 256>>>(out, sc3, sh3, total4);
}

// round 6
// speedup vs baseline: 1.4434x; 1.0104x over previous
#include <cuda_runtime.h>
#include <cstddef>

#define HDIM 64
#define NMAX 100352
#define EU_MAX 3300000
#define EB_MAX 350000

// ---------------- scratch (static device globals; no allocation allowed) ----
__device__ float g_aggu[(size_t)NMAX * HDIM];
__device__ float g_aggb[(size_t)NMAX * HDIM];
__device__ float g_y1u[(size_t)NMAX * HDIM];
__device__ float g_y1b[(size_t)NMAX * HDIM];
__device__ float g_y2[(size_t)NMAX * 2 * HDIM];
__device__ float g_stats[5 * 128];     // per BN: [0..63]=sum, [64..127]=sumsq
__device__ int g_degu[NMAX], g_degb[NMAX];
__device__ int g_offu[NMAX], g_offb[NMAX];
__device__ int g_curu[NMAX], g_curb[NMAX];
__device__ int g_part[2048];
__device__ int g_csru[EU_MAX];
__device__ int g_csrb[EB_MAX];

// ---------------- zero: degrees + stats -------------------------------------
__global__ void zero_kernel(int* __restrict__ degu, int* __restrict__ degb,
                            float* __restrict__ stats, int N)
{
    int i = blockIdx.x * blockDim.x + threadIdx.x;
    int stride = gridDim.x * blockDim.x;
    for (int t = i; t < N; t += stride) { degu[t] = 0; degb[t] = 0; }
    if (i < 5 * 128) stats[i] = 0.0f;
}

// ---------------- histogram of destination degrees --------------------------
__global__ void hist_kernel(const int* __restrict__ du, int EU,
                            const int* __restrict__ db, int EB,
                            int* __restrict__ degu, int* __restrict__ degb)
{
    long i = blockIdx.x * (long)blockDim.x + threadIdx.x;
    long stride = gridDim.x * (long)blockDim.x;
    long total = EU + EB;
    for (long t = i; t < total; t += stride) {
        if (t < EU) atomicAdd(&degu[__ldg(&du[t])], 1);
        else        atomicAdd(&degb[__ldg(&db[t - EU])], 1);
    }
}

// ---------------- scan stage 1: per-block totals ----------------------------
__global__ void scan1_kernel(const int* __restrict__ degu,
                             const int* __restrict__ degb,
                             int* __restrict__ part, int N)
{
    const int* deg = blockIdx.y ? degb : degu;
    __shared__ int sm[1024];
    int idx = blockIdx.x * 1024 + threadIdx.x;
    int v = (idx < N) ? deg[idx] : 0;
    sm[threadIdx.x] = v;
    __syncthreads();
    for (int o = 512; o > 0; o >>= 1) {
        if (threadIdx.x < o) sm[threadIdx.x] += sm[threadIdx.x + o];
        __syncthreads();
    }
    if (threadIdx.x == 0) part[blockIdx.y * 1024 + blockIdx.x] = sm[0];
}

// ---------------- scan stage 2: exclusive scan of partials (NB <= 1024) -----
__global__ void scan2_kernel(int* __restrict__ part, int NB)
{
    int y = blockIdx.y;
    int t = threadIdx.x;
    __shared__ int sm[2][1024];
    int v = (t < NB) ? part[y * 1024 + t] : 0;
    int c = 0;
    sm[0][t] = v;
    __syncthreads();
    for (int o = 1; o < 1024; o <<= 1) {
        int n = c ^ 1;
        int val = sm[c][t];
        if (t >= o) val += sm[c][t - o];
        sm[n][t] = val;
        __syncthreads();
        c = n;
    }
    if (t < NB) part[y * 1024 + t] = sm[c][t] - v;   // exclusive
}

// ---------------- scan stage 3: per-element offsets + cursor copy -----------
__global__ void scan3_kernel(const int* __restrict__ degu,
                             const int* __restrict__ degb,
                             const int* __restrict__ part,
                             int* __restrict__ offu, int* __restrict__ offb,
                             int* __restrict__ curu, int* __restrict__ curb,
                             int N)
{
    const int* deg = blockIdx.y ? degb : degu;
    int* offs = blockIdx.y ? offb : offu;
    int* curp = blockIdx.y ? curb : curu;
    int idx = blockIdx.x * 1024 + threadIdx.x;
    int t = threadIdx.x;
    __shared__ int sm[2][1024];
    int v = (idx < N) ? deg[idx] : 0;
    int c = 0;
    sm[0][t] = v;
    __syncthreads();
    for (int o = 1; o < 1024; o <<= 1) {
        int n = c ^ 1;
        int val = sm[c][t];
        if (t >= o) val += sm[c][t - o];
        sm[n][t] = val;
        __syncthreads();
        c = n;
    }
    int off = part[blockIdx.y * 1024 + blockIdx.x] + sm[c][t] - v;
    if (idx < N) { offs[idx] = off; curp[idx] = off; }
}

// ---------------- CSR fill ---------------------------------------------------
__global__ void fill_kernel(const int* __restrict__ du, const int* __restrict__ su, int EU,
                            const int* __restrict__ db, const int* __restrict__ sb, int EB,
                            int* __restrict__ curu, int* __restrict__ curb,
                            int* __restrict__ csru, int* __restrict__ csrb)
{
    long i = blockIdx.x * (long)blockDim.x + threadIdx.x;
    long stride = gridDim.x * (long)blockDim.x;
    long total = EU + EB;
    for (long t = i; t < total; t += stride) {
        if (t < EU) {
            int d = __ldg(&du[t]);
            int pos = atomicAdd(&curu[d], 1);
            csru[pos] = __ldg(&su[t]);
        } else {
            long tb = t - EU;
            int d = __ldg(&db[tb]);
            int pos = atomicAdd(&curb[d], 1);
            csrb[pos] = __ldg(&sb[tb]);
        }
    }
}

// ---------------- gather-aggregate (warp per dst) + fused (1+eps)*x init ----
__global__ void gather_kernel(const float* __restrict__ x,
                              const float* __restrict__ battr,
                              const int* __restrict__ offu, const int* __restrict__ degu,
                              const int* __restrict__ csru,
                              const int* __restrict__ offb, const int* __restrict__ degb,
                              const int* __restrict__ csrb,
                              const float* __restrict__ eps1,
                              const float* __restrict__ eps2,
                              float* __restrict__ aggu, float* __restrict__ aggb,
                              int N)
{
    int gw = (blockIdx.x * blockDim.x + threadIdx.x) >> 5;
    int lane = threadIdx.x & 31;
    if (gw >= N) return;
    bool up = (blockIdx.y == 0);
    const float* feat = up ? x : battr;
    const int* offs = up ? offu : offb;
    const int* deg  = up ? degu : degb;
    const int* csr  = up ? csru : csrb;
    float* agg = up ? aggu : aggb;
    float e = 1.0f + (up ? __ldg(eps1) : __ldg(eps2));

    int off = __ldg(&offs[gw]);
    int dg  = __ldg(&deg[gw]);
    float a0 = 0.f, a1 = 0.f;
    int i = 0;
    for (; i + 4 <= dg; i += 4) {
        int s0 = __ldg(&csr[off + i]);
        int s1 = __ldg(&csr[off + i + 1]);
        int s2 = __ldg(&csr[off + i + 2]);
        int s3 = __ldg(&csr[off + i + 3]);
        float u0 = __ldg(&feat[((size_t)s0 << 6) + lane]);
        float u1 = __ldg(&feat[((size_t)s1 << 6) + lane]);
        float u2 = __ldg(&feat[((size_t)s2 << 6) + lane]);
        float u3 = __ldg(&feat[((size_t)s3 << 6) + lane]);
        float v0 = __ldg(&feat[((size_t)s0 << 6) + lane + 32]);
        float v1 = __ldg(&feat[((size_t)s1 << 6) + lane + 32]);
        float v2 = __ldg(&feat[((size_t)s2 << 6) + lane + 32]);
        float v3 = __ldg(&feat[((size_t)s3 << 6) + lane + 32]);
        a0 += (u0 + u1) + (u2 + u3);
        a1 += (v0 + v1) + (v2 + v3);
    }
    for (; i < dg; i++) {
        int s0 = __ldg(&csr[off + i]);
        a0 += __ldg(&feat[((size_t)s0 << 6) + lane]);
        a1 += __ldg(&feat[((size_t)s0 << 6) + lane + 32]);
    }
    // self term is always x (reference: agg + (1+eps)*x)
    float b0 = e * __ldg(&x[((size_t)gw << 6) + lane]);
    float b1 = e * __ldg(&x[((size_t)gw << 6) + lane + 32]);
    agg[((size_t)gw << 6) + lane]      = a0 + b0;
    agg[((size_t)gw << 6) + lane + 32] = a1 + b1;
}

// ---------------- f32x2 helpers --------------------------------------------
__device__ __forceinline__ unsigned long long dup2(float v) {
    unsigned long long r;
    asm("mov.b64 %0, {%1, %1};" : "=l"(r) : "r"(__float_as_uint(v)));
    return r;
}
__device__ __forceinline__ void ffma2(unsigned long long& d,
                                      unsigned long long a,
                                      unsigned long long b) {
    asm("fma.rn.f32x2 %0, %1, %2, %0;" : "+l"(d) : "l"(a), "l"(b));
}
__device__ __forceinline__ float2 unpk(unsigned long long v) {
    unsigned int lo, hi;
    asm("mov.b64 {%0, %1}, %2;" : "=r"(lo), "=r"(hi) : "l"(v));
    return make_float2(__uint_as_float(lo), __uint_as_float(hi));
}

// ---------------- GEMM + bias + fused input BN(from stats)+ReLU + BN stats --
// Y[i][j] = sum_k act(A[i][k]) * W[k][j] + bias[j]
// AFF: in-kernel coeffs: scale = g*rsqrt(var+eps), shift = be - mean*scale,
//      computed per block from inStats/inG/inBe (two sets for K=128).
// Tile: 256 rows x 64 cols, 256 threads, 8x8 microtile, f32x2 packed math.
struct GArg {
    const float* A;
    const float* W;
    const float* bias;
    const float* inStats0; const float* inG0; const float* inBe0;
    const float* inStats1; const float* inG1; const float* inBe1;
    float* Y;
    float* stats;
};

template <int K, bool AFF>
__global__ __launch_bounds__(256, 2)
void gemm_bn(GArg ga, GArg gb, int ldY, int N, float invN)
{
    __shared__ float As[32][260];   // transposed A chunk: As[k][row]
    __shared__ float Ws[32][64];    // W chunk: Ws[k][col]
    __shared__ float sSc[AFF ? K : 1];
    __shared__ float sSh[AFF ? K : 1];

    const GArg g = (blockIdx.y == 0) ? ga : gb;

    const int tid  = threadIdx.x;         // 0..255
    const int lane = tid & 31;
    const int wy   = tid >> 5;            // col group (8 cols), 0..7
    const int rbase = blockIdx.x * 256;

    if (AFF) {
        if (tid < K) {
            const float* st = (tid < 64) ? g.inStats0 : g.inStats1;
            const float* gg = (tid < 64) ? g.inG0 : g.inG1;
            const float* bb = (tid < 64) ? g.inBe0 : g.inBe1;
            int j = tid & 63;
            float mean = st[j] * invN;
            float var  = st[64 + j] * invN - mean * mean;
            float s = gg[j] * rsqrtf(var + 1e-5f);
            sSc[tid] = s;
            sSh[tid] = bb[j] - mean * s;
        }
        __syncthreads();
    }

    unsigned long long acc[8][4];
#pragma unroll
    for (int i = 0; i < 8; i++)
#pragma unroll
        for (int p = 0; p < 4; p++) acc[i][p] = 0ull;

#pragma unroll
    for (int kc = 0; kc < K; kc += 32) {
        // --- load A chunk (256 rows x 32 cols), transform, transpose-store
#pragma unroll
        for (int it = 0; it < 8; it++) {
            int lin = it * 256 + tid;     // 2048 float4 slots
            int r   = lin >> 3;           // 8 float4 per row
            int c4  = lin & 7;
            int gr  = rbase + r;
            float4 v = make_float4(0.f, 0.f, 0.f, 0.f);
            if (gr < N)
                v = *(const float4*)&g.A[(size_t)gr * K + kc + c4 * 4];
            if (AFF) {
                int c = kc + c4 * 4;
                float4 s = *(const float4*)&sSc[c];
                float4 h = *(const float4*)&sSh[c];
                v.x = fmaxf(v.x * s.x + h.x, 0.f);
                v.y = fmaxf(v.y * s.y + h.y, 0.f);
                v.z = fmaxf(v.z * s.z + h.z, 0.f);
                v.w = fmaxf(v.w * s.w + h.w, 0.f);
            }
            As[c4 * 4 + 0][r] = v.x;
            As[c4 * 4 + 1][r] = v.y;
            As[c4 * 4 + 2][r] = v.z;
            As[c4 * 4 + 3][r] = v.w;
        }
        // --- load W chunk (32 rows x 64 cols)
#pragma unroll
        for (int it = 0; it < 2; it++) {
            int lin = it * 256 + tid;     // 512 float4
            int r   = lin >> 4;
            int c4  = lin & 15;
            *(float4*)&Ws[r][c4 * 4] = *(const float4*)&g.W[(size_t)(kc + r) * 64 + c4 * 4];
        }
        __syncthreads();

        // --- compute
#pragma unroll
        for (int k = 0; k < 32; k++) {
            float4 alo = *(const float4*)&As[k][lane * 4];
            float4 ahi = *(const float4*)&As[k][128 + lane * 4];
            ulonglong2 w03 = *(const ulonglong2*)&Ws[k][wy * 8];
            ulonglong2 w47 = *(const ulonglong2*)&Ws[k][wy * 8 + 4];
            unsigned long long wp[4] = { w03.x, w03.y, w47.x, w47.y };
            unsigned long long ad[8] = {
                dup2(alo.x), dup2(alo.y), dup2(alo.z), dup2(alo.w),
                dup2(ahi.x), dup2(ahi.y), dup2(ahi.z), dup2(ahi.w)
            };
#pragma unroll
            for (int i = 0; i < 8; i++)
#pragma unroll
                for (int p = 0; p < 4; p++)
                    ffma2(acc[i][p], ad[i], wp[p]);
        }
        if (kc + 32 < K) __syncthreads();
    }

    // --- epilogue
    float b[8];
    *(float4*)&b[0] = *(const float4*)&g.bias[wy * 8];
    *(float4*)&b[4] = *(const float4*)&g.bias[wy * 8 + 4];

    float psum[8], psq[8];
#pragma unroll
    for (int j = 0; j < 8; j++) { psum[j] = 0.f; psq[j] = 0.f; }

#pragma unroll
    for (int i = 0; i < 8; i++) {
        int gr = rbase + ((i < 4) ? (lane * 4 + i) : (128 + lane * 4 + i - 4));
        if (gr < N) {
            float v[8];
#pragma unroll
            for (int p = 0; p < 4; p++) {
                float2 t = unpk(acc[i][p]);
                v[2 * p + 0] = t.x + b[2 * p + 0];
                v[2 * p + 1] = t.y + b[2 * p + 1];
            }
#pragma unroll
            for (int j = 0; j < 8; j++) {
                psum[j] += v[j];
                psq[j]  += v[j] * v[j];
            }
            float* yp = &g.Y[(size_t)gr * ldY + wy * 8];
            *(float4*)&yp[0] = *(float4*)&v[0];
            *(float4*)&yp[4] = *(float4*)&v[4];
        }
    }
#pragma unroll
    for (int j = 0; j < 8; j++) {
#pragma unroll
        for (int o = 16; o > 0; o >>= 1) {
            psum[j] += __shfl_xor_sync(0xFFFFFFFFu, psum[j], o);
            psq[j]  += __shfl_xor_sync(0xFFFFFFFFu, psq[j],  o);
        }
    }
    if (lane == 0) {
#pragma unroll
        for (int j = 0; j < 8; j++) {
            atomicAdd(&g.stats[wy * 8 + j], psum[j]);
            atomicAdd(&g.stats[64 + wy * 8 + j], psq[j]);
        }
    }
}

// ---------------- final BN + ReLU with in-kernel coeffs ---------------------
__global__ void bnrelu_kernel(float* __restrict__ Y,
                              const float* __restrict__ stats,
                              const float* __restrict__ g,
                              const float* __restrict__ be,
                              int total4, float invN)
{
    __shared__ float sc[64], sh[64];
    if (threadIdx.x < 64) {
        int j = threadIdx.x;
        float mean = stats[j] * invN;
        float var  = stats[64 + j] * invN - mean * mean;
        float s = g[j] * rsqrtf(var + 1e-5f);
        sc[j] = s;
        sh[j] = be[j] - mean * s;
    }
    __syncthreads();
    int i = blockIdx.x * blockDim.x + threadIdx.x;
    int stride = gridDim.x * blockDim.x;
    float4* y4 = (float4*)Y;
    for (int t = i; t < total4; t += stride) {
        int c = (t * 4) & 63;
        float4 v = y4[t];
        float4 s = *(const float4*)&sc[c];
        float4 h = *(const float4*)&sh[c];
        v.x = fmaxf(v.x * s.x + h.x, 0.f);
        v.y = fmaxf(v.y * s.y + h.y, 0.f);
        v.z = fmaxf(v.z * s.z + h.z, 0.f);
        v.w = fmaxf(v.w * s.w + h.w, 0.f);
        y4[t] = v;
    }
}

// ---------------- launch ----------------------------------------------------
extern "C" void kernel_launch(void* const* d_in, const int* in_sizes, int n_in,
                              void* d_out, int out_size)
{
    const float* x     = (const float*)d_in[0];
    const float* battr = (const float*)d_in[1];
    const int*   upidx = (const int*)d_in[2];
    const int*   bidx  = (const int*)d_in[3];
    const float* eps1  = (const float*)d_in[4];
    const float* eps2  = (const float*)d_in[5];
    const float* uw1 = (const float*)d_in[6];
    const float* ub1 = (const float*)d_in[7];
    const float* ug1 = (const float*)d_in[8];
    const float* ube1= (const float*)d_in[9];
    const float* uw2 = (const float*)d_in[10];
    const float* ub2 = (const float*)d_in[11];
    const float* ug2 = (const float*)d_in[12];
    const float* ube2= (const float*)d_in[13];
    const float* bw1 = (const float*)d_in[14];
    const float* bb1 = (const float*)d_in[15];
    const float* bg1 = (const float*)d_in[16];
    const float* bbe1= (const float*)d_in[17];
    const float* bw2 = (const float*)d_in[18];
    const float* bb2 = (const float*)d_in[19];
    const float* bg2 = (const float*)d_in[20];
    const float* bbe2= (const float*)d_in[21];
    const float* cw  = (const float*)d_in[22];
    const float* cb  = (const float*)d_in[23];
    const float* cg  = (const float*)d_in[24];
    const float* cbe = (const float*)d_in[25];
    float* out = (float*)d_out;

    int N  = in_sizes[0] / HDIM;
    int EU = in_sizes[2] / 2;
    int EB = in_sizes[3] / 2;

    float *aggu, *aggb, *y1u, *y1b, *y2, *stats;
    int *degu, *degb, *offu, *offb, *curu, *curb, *part, *csru, *csrb;
    cudaGetSymbolAddress((void**)&aggu,  g_aggu);
    cudaGetSymbolAddress((void**)&aggb,  g_aggb);
    cudaGetSymbolAddress((void**)&y1u,   g_y1u);
    cudaGetSymbolAddress((void**)&y1b,   g_y1b);
    cudaGetSymbolAddress((void**)&y2,    g_y2);
    cudaGetSymbolAddress((void**)&stats, g_stats);
    cudaGetSymbolAddress((void**)&degu,  g_degu);
    cudaGetSymbolAddress((void**)&degb,  g_degb);
    cudaGetSymbolAddress((void**)&offu,  g_offu);
    cudaGetSymbolAddress((void**)&offb,  g_offb);
    cudaGetSymbolAddress((void**)&curu,  g_curu);
    cudaGetSymbolAddress((void**)&curb,  g_curb);
    cudaGetSymbolAddress((void**)&part,  g_part);
    cudaGetSymbolAddress((void**)&csru,  g_csru);
    cudaGetSymbolAddress((void**)&csrb,  g_csrb);

    float invN = 1.0f / (float)N;
    int total4 = (N * HDIM) / 4;
    int gb = (N + 255) / 256;
    int NB = (N + 1023) / 1024;

    // edge index rows:
    // up:       dst = upidx[0..EU),   src = upidx[EU..2EU)
    // boundary: dst = bidx[EB..2EB),  src = bidx[0..EB)
    const int* du = upidx;
    const int* su = upidx + EU;
    const int* db = bidx + EB;
    const int* sb = bidx;

    // Phase 0: CSR build
    zero_kernel<<<256, 256>>>(degu, degb, stats, N);
    hist_kernel<<<4096, 256>>>(du, EU, db, EB, degu, degb);
    scan1_kernel<<<dim3(NB, 2), 1024>>>(degu, degb, part, N);
    scan2_kernel<<<dim3(1, 2), 1024>>>(part, NB);
    scan3_kernel<<<dim3(NB, 2), 1024>>>(degu, degb, part, offu, offb, curu, curb, N);
    fill_kernel<<<4096, 256>>>(du, su, EU, db, sb, EB, curu, curb, csru, csrb);

    // Phase 1: gather-aggregate (fused (1+eps)*x self term)
    gather_kernel<<<dim3((N + 7) / 8, 2), 256>>>(
        x, battr, offu, degu, csru, offb, degb, csrb, eps1, eps2, aggu, aggb, N);

    // Phase 2: layer-1 GEMMs (merged dual launch, + BN stats)
    {
        GArg gu = { aggu, uw1, ub1, nullptr, nullptr, nullptr,
                    nullptr, nullptr, nullptr, y1u, stats + 0 };
        GArg gv = { aggb, bw1, bb1, nullptr, nullptr, nullptr,
                    nullptr, nullptr, nullptr, y1b, stats + 128 };
        gemm_bn<64, false><<<dim3(gb, 2), 256>>>(gu, gv, 64, N, invN);
    }

    // Phase 3: layer-2 GEMMs, input BN+ReLU from stats computed in-kernel
    {
        GArg gu = { y1u, uw2, ub2, stats + 0,   ug1, ube1,
                    stats + 0,   ug1, ube1, y2,      stats + 256 };
        GArg gv = { y1b, bw2, bb2, stats + 128, bg1, bbe1,
                    stats + 128, bg1, bbe1, y2 + 64, stats + 384 };
        gemm_bn<64, true><<<dim3(gb, 2), 256>>>(gu, gv, 128, N, invN);
    }

    // Phase 4: combine GEMM (K=128), input BN+ReLU from two stats sets
    {
        GArg gc = { y2, cw, cb, stats + 256, ug2, ube2,
                    stats + 384, bg2, bbe2, out, stats + 512 };
        gemm_bn<128, true><<<dim3(gb, 1), 256>>>(gc, gc, 64, N, invN);
    }

    // Phase 5: final BN+ReLU in place on out (coeffs in-kernel)
    bnrelu_kernel<<<592, 256>>>(out, stats + 512, cg, cbe, total4, invN);
}